// round 15
// baseline (speedup 1.0000x reference)
#include <cuda_runtime.h>
#include <cuda_bf16.h>
#include <cstdint>
#include <math.h>

#define NB   32
#define NEVI 5
#define NN   160
#define LL   130
#define HH   768
#define KK   21
#define ROWS 650
#define NT   6
#define NPAIR 21
#define GRAM_SMEM 98304
#define GATE_SMEM 90624

__device__ float g_mt  [NN*LL];
__device__ float g_mc  [NN*LL];
__device__ float g_mev [NN*LL];
__device__ __nv_bfloat16 g_hbf[(size_t)NB*ROWS*HH];
__device__ float g_G   [(size_t)NB*ROWS*ROWS + 4096];
__device__ float g_sel [NN];
__device__ float g_att [NN*NEVI*LL];
__device__ float g_den [NEVI*NB*NEVI*HH];
__device__ float g_de  [NEVI*NB*HH];

#define C0F (-721347.5204444817f)
#define C2F (-72.13475204444817f)

__device__ __forceinline__ float ex2f(float x){
    float y; asm("ex2.approx.ftz.f32 %0, %1;" : "=f"(y) : "f"(x)); return y;
}
__device__ __forceinline__ float warp_sum(float v){
    #pragma unroll
    for (int s = 16; s; s >>= 1) v += __shfl_xor_sync(0xffffffffu, v, s);
    return v;
}
__device__ __forceinline__ float warp_max(float v){
    #pragma unroll
    for (int s = 16; s; s >>= 1) v = fmaxf(v, __shfl_xor_sync(0xffffffffu, v, s));
    return v;
}

// ---------------- packed f32x2 helpers ----------------
__device__ __forceinline__ unsigned long long pk(float lo, float hi){
    unsigned long long r; asm("mov.b64 %0, {%1,%2};" : "=l"(r) : "f"(lo), "f"(hi)); return r;
}
__device__ __forceinline__ void upk(unsigned long long v, float& lo, float& hi){
    asm("mov.b64 {%0,%1}, %2;" : "=f"(lo), "=f"(hi) : "l"(v));
}
__device__ __forceinline__ unsigned long long pmul(unsigned long long a, unsigned long long b){
    unsigned long long r; asm("mul.rn.f32x2 %0, %1, %2;" : "=l"(r) : "l"(a), "l"(b)); return r;
}
__device__ __forceinline__ unsigned long long padd(unsigned long long a, unsigned long long b){
    unsigned long long r; asm("add.rn.f32x2 %0, %1, %2;" : "=l"(r) : "l"(a), "l"(b)); return r;
}

struct PoolC {
    unsigned long long PM1, PMU, PC0, PC2, PL, PE1, PE3, PE4, PE5;
};
__device__ __forceinline__ PoolC make_poolc(){
    PoolC c;
    c.PM1 = pk(-1.f, -1.f);
    c.PMU = pk(-0.05f, -0.05f);
    c.PC0 = pk(C0F, C0F);
    c.PC2 = pk(C2F, C2F);
    c.PL  = pk(14.426950408889634f, 14.426950408889634f);
    c.PE1 = pk(0.36787944117144233f, 0.36787944117144233f);
    c.PE3 = pk(0.049787068367863944f, 0.049787068367863944f);
    c.PE4 = pk(0.018315638888734179f, 0.018315638888734179f);
    c.PE5 = pk(0.006737946999085467f, 0.006737946999085467f);
    return c;
}

__device__ __forceinline__ void pool_step(const PoolC& C, float s0, float s1,
                                          unsigned long long m2,
                                          unsigned long long* acc){
    unsigned long long s2 = pk(s0, s1);
    unsigned long long t0 = padd(s2, C.PM1);
    unsigned long long x  = pmul(pmul(t0, C.PC0), t0);
    float xl, xh; upk(x, xl, xh);
    unsigned long long E = pmul(pk(ex2f(xl), ex2f(xh)), m2);
    acc[0] = padd(acc[0], E);
    unsigned long long tm = padd(s2, C.PMU);
    x = pmul(pmul(tm, C.PC2), tm);
    upk(x, xl, xh);
    unsigned long long T = pmul(pk(ex2f(xl), ex2f(xh)), m2);
    acc[10] = padd(acc[10], T);
    unsigned long long y = pmul(s2, C.PL);
    upk(y, xl, xh);
    unsigned long long Rup = pk(ex2f(xl), ex2f(xh));
    unsigned long long Rdn = pk(ex2f(-xl), ex2f(-xh));
    {
        unsigned long long R2 = pmul(Rdn, Rdn);
        unsigned long long tO = pmul(T, Rdn);
        acc[11] = padd(acc[11], tO);
        unsigned long long U = pmul(R2, C.PE1);
        unsigned long long V = pmul(R2, C.PE3);
        unsigned long long tE = T;
        #pragma unroll
        for (int m = 0; m < 5; m++){
            tE = pmul(tE, U);
            acc[12+2*m] = padd(acc[12+2*m], tE);
            if (m < 4){
                tO = pmul(tO, V);
                acc[13+2*m] = padd(acc[13+2*m], tO);
                U = pmul(U, C.PE4);
                V = pmul(V, C.PE4);
            }
        }
    }
    {
        unsigned long long S2 = pmul(Rup, Rup);
        unsigned long long tO = pmul(pmul(T, Rup), C.PE1);
        acc[9] = padd(acc[9], tO);
        unsigned long long U = pmul(S2, C.PE3);
        unsigned long long V = pmul(S2, C.PE5);
        unsigned long long tE = T;
        #pragma unroll
        for (int m = 0; m < 4; m++){
            tE = pmul(tE, U);
            acc[8-2*m] = padd(acc[8-2*m], tE);
            tO = pmul(tO, V);
            acc[7-2*m] = padd(acc[7-2*m], tO);
            if (m < 3){
                U = pmul(U, C.PE4);
                V = pmul(V, C.PE4);
            }
        }
    }
}

__device__ __forceinline__ void pool_step2(const PoolC& C,
                                           float s0, float s1, float s2v, float s3,
                                           unsigned long long m2a,
                                           unsigned long long m2b,
                                           unsigned long long* acc){
    unsigned long long sa = pk(s0, s1), sb = pk(s2v, s3);
    unsigned long long ta0 = padd(sa, C.PM1), tb0 = padd(sb, C.PM1);
    unsigned long long xa = pmul(pmul(ta0, C.PC0), ta0);
    unsigned long long xb = pmul(pmul(tb0, C.PC0), tb0);
    float al, ah, bl, bh;
    upk(xa, al, ah); upk(xb, bl, bh);
    unsigned long long Ea = pmul(pk(ex2f(al), ex2f(ah)), m2a);
    unsigned long long Eb = pmul(pk(ex2f(bl), ex2f(bh)), m2b);
    acc[0] = padd(acc[0], padd(Ea, Eb));
    unsigned long long tma = padd(sa, C.PMU), tmb = padd(sb, C.PMU);
    xa = pmul(pmul(tma, C.PC2), tma);
    xb = pmul(pmul(tmb, C.PC2), tmb);
    upk(xa, al, ah); upk(xb, bl, bh);
    unsigned long long Ta = pmul(pk(ex2f(al), ex2f(ah)), m2a);
    unsigned long long Tb = pmul(pk(ex2f(bl), ex2f(bh)), m2b);
    acc[10] = padd(acc[10], padd(Ta, Tb));
    unsigned long long ya = pmul(sa, C.PL), yb = pmul(sb, C.PL);
    upk(ya, al, ah); upk(yb, bl, bh);
    unsigned long long RupA = pk(ex2f(al), ex2f(ah));
    unsigned long long RdnA = pk(ex2f(-al), ex2f(-ah));
    unsigned long long RupB = pk(ex2f(bl), ex2f(bh));
    unsigned long long RdnB = pk(ex2f(-bl), ex2f(-bh));
    {
        unsigned long long R2a = pmul(RdnA, RdnA), R2b = pmul(RdnB, RdnB);
        unsigned long long tOa = pmul(Ta, RdnA),  tOb = pmul(Tb, RdnB);
        acc[11] = padd(acc[11], padd(tOa, tOb));
        unsigned long long Ua = pmul(R2a, C.PE1), Ub = pmul(R2b, C.PE1);
        unsigned long long Va = pmul(R2a, C.PE3), Vb = pmul(R2b, C.PE3);
        unsigned long long tEa = Ta, tEb = Tb;
        #pragma unroll
        for (int m = 0; m < 5; m++){
            tEa = pmul(tEa, Ua); tEb = pmul(tEb, Ub);
            acc[12+2*m] = padd(acc[12+2*m], padd(tEa, tEb));
            if (m < 4){
                tOa = pmul(tOa, Va); tOb = pmul(tOb, Vb);
                acc[13+2*m] = padd(acc[13+2*m], padd(tOa, tOb));
                Ua = pmul(Ua, C.PE4); Ub = pmul(Ub, C.PE4);
                Va = pmul(Va, C.PE4); Vb = pmul(Vb, C.PE4);
            }
        }
    }
    {
        unsigned long long S2a = pmul(RupA, RupA), S2b = pmul(RupB, RupB);
        unsigned long long tOa = pmul(pmul(Ta, RupA), C.PE1);
        unsigned long long tOb = pmul(pmul(Tb, RupB), C.PE1);
        acc[9] = padd(acc[9], padd(tOa, tOb));
        unsigned long long Ua = pmul(S2a, C.PE3), Ub = pmul(S2b, C.PE3);
        unsigned long long Va = pmul(S2a, C.PE5), Vb = pmul(S2b, C.PE5);
        unsigned long long tEa = Ta, tEb = Tb;
        #pragma unroll
        for (int m = 0; m < 4; m++){
            tEa = pmul(tEa, Ua); tEb = pmul(tEb, Ub);
            acc[8-2*m] = padd(acc[8-2*m], padd(tEa, tEb));
            tOa = pmul(tOa, Va); tOb = pmul(tOb, Vb);
            acc[7-2*m] = padd(acc[7-2*m], padd(tOa, tOb));
            if (m < 3){
                Ua = pmul(Ua, C.PE4); Ub = pmul(Ub, C.PE4);
                Va = pmul(Va, C.PE4); Vb = pmul(Vb, C.PE4);
            }
        }
    }
}

// K1: norms, masks, bf16 normalized copy (row range [base, base+gridDim.x))
__global__ void k_norm(const float* __restrict__ hid,
                       const int* __restrict__ msk,
                       const int* __restrict__ seg,
                       int base){
    int row = blockIdx.x + base;
    const float* x = hid + (size_t)row*HH;
    int tid = threadIdx.x;
    float v0 = x[tid], v1 = x[tid+256], v2 = x[tid+512];
    float ss = v0*v0 + v1*v1 + v2*v2;
    ss = warp_sum(ss);
    __shared__ float wsum[8];
    __shared__ float sinv;
    if ((tid & 31) == 0) wsum[tid>>5] = ss;
    __syncthreads();
    if (tid == 0){
        float tot = 0.f;
        #pragma unroll
        for (int w = 0; w < 8; w++) tot += wsum[w];
        sinv = 1.0f / fmaxf(sqrtf(tot), 1e-12f);
        int l = row % LL;
        float mt = (l == 0) ? 0.f : (float)msk[row];
        float sf = (float)seg[row];
        g_mt[row]  = mt;
        g_mc[row]  = (1.f - sf) * mt;
        g_mev[row] = sf * mt;
    }
    __syncthreads();
    float iv = sinv;
    __nv_bfloat16* dst = g_hbf + (size_t)row*HH;
    dst[tid]     = __float2bfloat16(v0*iv);
    dst[tid+256] = __float2bfloat16(v1*iv);
    dst[tid+512] = __float2bfloat16(v2*iv);
}

// K2: bf16 HMMA symmetric Gram, 3-stage cp.async pipeline, coalesced epilogue
__device__ __forceinline__ void cpasync16(unsigned dst, const void* src, int sz){
    asm volatile("cp.async.cg.shared.global [%0], [%1], 16, %2;"
                 :: "r"(dst), "l"(src), "r"(sz));
}
__device__ __forceinline__ void ldsm_x4(unsigned& r0, unsigned& r1,
                                        unsigned& r2, unsigned& r3, unsigned a){
    asm volatile("ldmatrix.sync.aligned.m8n8.x4.shared.b16 {%0,%1,%2,%3}, [%4];"
                 : "=r"(r0), "=r"(r1), "=r"(r2), "=r"(r3) : "r"(a));
}
__device__ __forceinline__ void mma16816(float* c, unsigned a0, unsigned a1,
                                         unsigned a2, unsigned a3,
                                         unsigned b0, unsigned b1){
    asm volatile(
      "mma.sync.aligned.m16n8k16.row.col.f32.bf16.bf16.f32 "
      "{%0,%1,%2,%3}, {%4,%5,%6,%7}, {%8,%9}, {%0,%1,%2,%3};"
      : "+f"(c[0]), "+f"(c[1]), "+f"(c[2]), "+f"(c[3])
      : "r"(a0), "r"(a1), "r"(a2), "r"(a3), "r"(b0), "r"(b1));
}

__global__ void __launch_bounds__(256) k_gram(){
    extern __shared__ __align__(16) unsigned char dynsm[];
    unsigned sbase = (unsigned)__cvta_generic_to_shared(dynsm);

    int p = blockIdx.x, b = blockIdx.y;
    int ti = 0, rem = p;
    while (rem >= NT - ti){ rem -= NT - ti; ti++; }
    int tj = ti + rem;

    const __nv_bfloat16* Xb = g_hbf + (size_t)b*ROWS*HH;
    float* Gb = g_G + (size_t)b*ROWS*ROWS;

    int tid  = threadIdx.x;
    int lane = tid & 31, wid = tid >> 5;
    int wr = wid >> 2, wc = wid & 3;

    int lrow = tid >> 1;
    int cb   = (tid & 1) * 4;
    unsigned off[4];
    #pragma unroll
    for (int j = 0; j < 4; j++)
        off[j] = (unsigned)(lrow*128 + (((cb+j) ^ (lrow & 7)) * 16));

    int grA = ti*128 + lrow; bool okA = grA < ROWS;
    int grB = tj*128 + lrow; bool okB = grB < ROWS;
    const char* bsA = (const char*)(Xb + (size_t)(okA ? grA : 0)*HH) + cb*16;
    const char* bsB = (const char*)(Xb + (size_t)(okB ? grB : 0)*HH) + cb*16;
    int szA = okA ? 16 : 0, szB = okB ? 16 : 0;

    int arow = wr*64 + (lane & 15);
    int ahalf = lane >> 4;
    int arsw = arow & 7;
    int brow = wc*32 + ((lane >> 4) & 1)*8 + (lane & 7);
    int bhalf = (lane >> 3) & 1;
    int brsw = lane & 7;

    float acc[4][4][4];
    #pragma unroll
    for (int mi = 0; mi < 4; mi++)
        #pragma unroll
        for (int ni = 0; ni < 4; ni++)
            #pragma unroll
            for (int r = 0; r < 4; r++) acc[mi][ni][r] = 0.f;

    const int NCH = HH / 64;   // 12 chunks

    #pragma unroll
    for (int pc = 0; pc < 2; pc++){
        unsigned st = sbase + pc*32768;
        const char* sA = bsA + (size_t)pc*128;
        const char* sB = bsB + (size_t)pc*128;
        #pragma unroll
        for (int j = 0; j < 4; j++){
            cpasync16(st + off[j],         sA + j*16, szA);
            cpasync16(st + 16384 + off[j], sB + j*16, szB);
        }
        asm volatile("cp.async.commit_group;" ::: "memory");
    }

    for (int i = 0; i < NCH; i++){
        if (i + 2 < NCH){
            int s2 = (i + 2) % 3;
            unsigned st = sbase + s2*32768;
            const char* sA = bsA + (size_t)(i+2)*128;
            const char* sB = bsB + (size_t)(i+2)*128;
            #pragma unroll
            for (int j = 0; j < 4; j++){
                cpasync16(st + off[j],         sA + j*16, szA);
                cpasync16(st + 16384 + off[j], sB + j*16, szB);
            }
            asm volatile("cp.async.commit_group;" ::: "memory");
            asm volatile("cp.async.wait_group 2;" ::: "memory");
        } else if (i + 1 < NCH){
            asm volatile("cp.async.wait_group 1;" ::: "memory");
        } else {
            asm volatile("cp.async.wait_group 0;" ::: "memory");
        }
        __syncthreads();

        unsigned stA = sbase + (i % 3)*32768;
        unsigned stB = stA + 16384;
        #pragma unroll
        for (int ks = 0; ks < 4; ks++){
            unsigned bfr[4][2];
            unsigned adB0 = stB + (unsigned)((brow)*128      + (((2*ks + bhalf) ^ brsw)*16));
            unsigned adB1 = stB + (unsigned)((brow + 16)*128 + (((2*ks + bhalf) ^ brsw)*16));
            ldsm_x4(bfr[0][0], bfr[0][1], bfr[1][0], bfr[1][1], adB0);
            ldsm_x4(bfr[2][0], bfr[2][1], bfr[3][0], bfr[3][1], adB1);
            #pragma unroll
            for (int mi = 0; mi < 4; mi++){
                unsigned a0, a1, a2, a3;
                unsigned adA = stA + (unsigned)((arow + mi*16)*128 + (((2*ks + ahalf) ^ arsw)*16));
                ldsm_x4(a0, a1, a2, a3, adA);
                #pragma unroll
                for (int ni = 0; ni < 4; ni++)
                    mma16816(acc[mi][ni], a0, a1, a2, a3, bfr[ni][0], bfr[ni][1]);
            }
        }
        __syncthreads();
    }

    float* T = (float*)dynsm;
    int trow = lane >> 2;
    int tcol = (lane & 3) * 2;
    bool diag = (ti == tj);
    #pragma unroll
    for (int mi = 0; mi < 4; mi++){
        #pragma unroll
        for (int ni = 0; ni < 4; ni++){
            #pragma unroll
            for (int half = 0; half < 2; half++){
                int rl = wr*64 + mi*16 + trow + half*8;
                #pragma unroll
                for (int u = 0; u < 2; u++){
                    int cl = wc*32 + ni*8 + tcol + u;
                    float v = acc[mi][ni][half*2 + u];
                    if (diag && rl == cl) v = 1.0f;
                    T[rl*129 + cl] = v;
                }
            }
        }
    }
    __syncthreads();

    for (int idx = tid; idx < 128*128; idx += 256){
        int rl = idx >> 7, cl = idx & 127;
        int r = ti*128 + rl, c = tj*128 + cl;
        if (r < ROWS && c < ROWS)
            Gb[(size_t)r*ROWS + c] = T[rl*129 + cl];
    }
    if (!diag){
        #pragma unroll
        for (int cc = 0; cc < 16; cc++){
            int cl = wid*16 + cc;
            int grow = tj*128 + cl;
            if (grow < ROWS){
                float* gdst = Gb + (size_t)grow*ROWS + ti*128;
                #pragma unroll
                for (int rr = 0; rr < 4; rr++){
                    int rl = rr*32 + lane;
                    gdst[rl] = T[rl*129 + cl];
                }
            }
        }
    }
}

// K3: fused pooling — y=0..4: attention score+softmax (i=y); y=5: sel
__global__ void __launch_bounds__(160) k_pool(const float* __restrict__ Watt,
                                              const float* __restrict__ batt,
                                              const float* __restrict__ Wsel,
                                              const float* __restrict__ bsel){
    int n = blockIdx.x, iy = blockIdx.y;
    int b = n / NEVI, e = n % NEVI;
    bool is_sel = (iy == 5);
    int rb = is_sel ? e : iy;
    int tid = threadIdx.x, lane = tid & 31, wid = tid >> 5;
    bool act = tid < LL;
    int q = act ? tid : 0;

    __shared__ __align__(8) float smsk[132];
    __shared__ float swv[KK];
    __shared__ float redA[5], redB[5];
    if (tid < KK) swv[tid] = is_sel ? Wsel[tid] : Watt[tid];
    if (tid < LL) smsk[tid] = is_sel ? g_mev[n*LL + tid]
                                     : g_mt[(b*NEVI + iy)*LL + tid];
    if (tid >= LL && tid < 132) smsk[tid] = 0.f;
    __syncthreads();

    const float* gcol = g_G + (size_t)b*ROWS*ROWS + (size_t)(rb*LL)*ROWS + (e*LL + q);
    PoolC C = make_poolc();
    unsigned long long acc[KK];
    #pragma unroll
    for (int k = 0; k < KK; k++) acc[k] = 0ull;

    #pragma unroll 1
    for (int d = 0; d < 128; d += 4){
        float s0 = gcol[(size_t)(d+0)*ROWS];
        float s1 = gcol[(size_t)(d+1)*ROWS];
        float s2 = gcol[(size_t)(d+2)*ROWS];
        float s3 = gcol[(size_t)(d+3)*ROWS];
        unsigned long long m2a = *(const unsigned long long*)(smsk + d);
        unsigned long long m2b = *(const unsigned long long*)(smsk + d + 2);
        pool_step2(C, s0, s1, s2, s3, m2a, m2b, acc);
    }
    {
        float s0 = gcol[(size_t)128*ROWS];
        float s1 = gcol[(size_t)129*ROWS];
        unsigned long long m2 = *(const unsigned long long*)(smsk + 128);
        pool_step(C, s0, s1, m2, acc);
    }

    if (is_sel){
        float mcq = act ? g_mc[n*LL + q] : 0.f;
        float contrib = 0.f;
        if (mcq > 0.f){
            float sq = 0.f;
            #pragma unroll
            for (int k = 0; k < KK; k++){
                float lo, hi; upk(acc[k], lo, hi);
                float pp = lo + hi;
                sq = fmaf(swv[k], __logf(fmaxf(pp, 1e-10f)), sq);
            }
            contrib = mcq * sq;
        }
        float nume = warp_sum(contrib);
        float deno = warp_sum(mcq);
        if (lane == 0){ redA[wid] = nume; redB[wid] = deno; }
        __syncthreads();
        if (tid == 0){
            float tn = 0.f, td = 0.f;
            #pragma unroll
            for (int w = 0; w < 5; w++){ tn += redA[w]; td += redB[w]; }
            g_sel[n] = tn / (td + 1e-10f) + bsel[0];
        }
    } else {
        float sv = -1e30f;
        if (act){
            float mtq = g_mt[n*LL + q];
            if (mtq > 0.f){
                sv = batt[0];
                #pragma unroll
                for (int k = 0; k < KK; k++){
                    float lo, hi; upk(acc[k], lo, hi);
                    float pp = lo + hi;
                    sv = fmaf(swv[k], __logf(fmaxf(pp, 1e-10f)), sv);
                }
            } else {
                sv = -10000.f;
            }
        }
        float mval = warp_max(sv);
        if (lane == 0) redA[wid] = mval;
        __syncthreads();
        float mx = redA[0];
        #pragma unroll
        for (int w = 1; w < 5; w++) mx = fmaxf(mx, redA[w]);
        float ev = act ? __expf(sv - mx) : 0.f;
        float sum = warp_sum(ev);
        if (lane == 0) redB[wid] = sum;
        __syncthreads();
        float tot = redB[0] + redB[1] + redB[2] + redB[3] + redB[4];
        if (act) g_att[(n*NEVI + iy)*LL + q] = ev / tot;
    }
}

// K4: denoise — grid (NN, 6): 128-col slabs, deep MLP
__global__ void __launch_bounds__(128) k_denoise(const float* __restrict__ hid){
    int n = blockIdx.x;
    int hoff = blockIdx.y << 7;
    int b = n / NEVI, e = n % NEVI;
    int tid = threadIdx.x;
    __shared__ float satt[NEVI*LL];
    for (int idx = tid; idx < NEVI*LL; idx += 128)
        satt[idx] = g_att[n*NEVI*LL + idx];
    __syncthreads();

    float a0 = 0.f, a1 = 0.f, a2 = 0.f, a3 = 0.f, a4 = 0.f;
    const float* hb = hid + (size_t)n*LL*HH + hoff + tid;
    #pragma unroll 1
    for (int q = 0; q < 128; q += 8){
        float h[8];
        #pragma unroll
        for (int u = 0; u < 8; u++) h[u] = hb[(size_t)(q+u)*HH];
        #pragma unroll
        for (int u = 0; u < 8; u++){
            const float* sa = satt + (q+u);
            a0 = fmaf(sa[0*LL], h[u], a0);
            a1 = fmaf(sa[1*LL], h[u], a1);
            a2 = fmaf(sa[2*LL], h[u], a2);
            a3 = fmaf(sa[3*LL], h[u], a3);
            a4 = fmaf(sa[4*LL], h[u], a4);
        }
    }
    #pragma unroll
    for (int q = 128; q < LL; q++){
        float h = hb[(size_t)q*HH];
        a0 = fmaf(satt[0*LL + q], h, a0);
        a1 = fmaf(satt[1*LL + q], h, a1);
        a2 = fmaf(satt[2*LL + q], h, a2);
        a3 = fmaf(satt[3*LL + q], h, a3);
        a4 = fmaf(satt[4*LL + q], h, a4);
    }
    size_t be = (size_t)b*NEVI + e;
    g_den[(0*(size_t)NB*NEVI + be)*HH + hoff + tid] = a0;
    g_den[(1*(size_t)NB*NEVI + be)*HH + hoff + tid] = a1;
    g_den[(2*(size_t)NB*NEVI + be)*HH + hoff + tid] = a2;
    g_den[(3*(size_t)NB*NEVI + be)*HH + hoff + tid] = a3;
    g_den[(4*(size_t)NB*NEVI + be)*HH + hoff + tid] = a4;
}

// K5: gate MLP + combine — smem-tiled Wg1 (coalesced), 256 threads
__global__ void __launch_bounds__(256) k_gate(
        const float* __restrict__ pooled,
        const float* __restrict__ Wg1, const float* __restrict__ bg1,
        const float* __restrict__ Wg2, const float* __restrict__ bg2){
    extern __shared__ __align__(16) float gsm[];
    float* smW  = gsm;
    float* sp   = gsm + 128*129;
    float* sden = sp + HH;
    float* pacc = sden + NEVI*HH;
    float* pe   = pacc + 256;
    __shared__ float gate[NEVI], wrs[8], wsm[NEVI];

    int i = blockIdx.x, b = blockIdx.y;
    int tid = threadIdx.x, lane = tid & 31, wid = tid >> 5;
    int j = tid & 127, h = tid >> 7;

    const float* pv = pooled + (size_t)(b*NEVI + i)*HH;
    for (int t = tid; t < HH; t += 256) sp[t] = pv[t];
    const float* dsrc = g_den + (size_t)(i*NB + b)*NEVI*HH;
    for (int idx = tid; idx < NEVI*HH; idx += 256) sden[idx] = dsrc[idx];
    __syncthreads();

    float accp = 0.f;
    float acce[NEVI];
    #pragma unroll
    for (int e = 0; e < NEVI; e++) acce[e] = 0.f;

    for (int tt = 0; tt < 12; tt++){
        #pragma unroll
        for (int k = 0; k < 16; k++){
            int lin = tid + k*256;
            int j2 = lin >> 5, c4 = lin & 31;
            float4 v = *(const float4*)(Wg1 + (size_t)j2*(2*HH) + tt*128 + c4*4);
            float* d = smW + j2*129 + c4*4;
            d[0]=v.x; d[1]=v.y; d[2]=v.z; d[3]=v.w;
        }
        __syncthreads();
        const float* wv = smW + j*129 + h*64;
        if (tt < 6){
            const float* svv = sp + tt*128 + h*64;
            #pragma unroll 8
            for (int t = 0; t < 64; t++) accp = fmaf(wv[t], svv[t], accp);
        } else {
            const float* s0 = sden + (tt-6)*128 + h*64;
            #pragma unroll 4
            for (int t = 0; t < 64; t++){
                float w = wv[t];
                acce[0] = fmaf(w, s0[t],          acce[0]);
                acce[1] = fmaf(w, s0[HH + t],     acce[1]);
                acce[2] = fmaf(w, s0[2*HH + t],   acce[2]);
                acce[3] = fmaf(w, s0[3*HH + t],   acce[3]);
                acce[4] = fmaf(w, s0[4*HH + t],   acce[4]);
            }
        }
        __syncthreads();
    }

    pacc[h*128 + j] = accp;
    #pragma unroll
    for (int e = 0; e < NEVI; e++) pe[(h*128 + j)*NEVI + e] = acce[e];
    __syncthreads();

    float bj = 0.f, w2 = 0.f;
    if (h == 0){
        accp = pacc[j] + pacc[128 + j];
        #pragma unroll
        for (int e = 0; e < NEVI; e++)
            acce[e] = pe[j*NEVI + e] + pe[(128 + j)*NEVI + e];
        bj = bg1[j]; w2 = Wg2[j];
    }
    for (int e = 0; e < NEVI; e++){
        float c = 0.f;
        if (h == 0){
            float g1 = fmaxf(accp + acce[e] + bj, 0.f);
            c = g1 * w2;
        }
        c = warp_sum(c);
        if (lane == 0) wrs[wid] = c;
        __syncthreads();
        if (tid == 0) gate[e] = wrs[0] + wrs[1] + wrs[2] + wrs[3] + bg2[0];
        __syncthreads();
    }
    if (tid == 0){
        float mx = gate[0];
        #pragma unroll
        for (int e = 1; e < NEVI; e++) mx = fmaxf(mx, gate[e]);
        float s = 0.f;
        #pragma unroll
        for (int e = 0; e < NEVI; e++){ wsm[e] = __expf(gate[e] - mx); s += wsm[e]; }
        float invs = 1.f / s;
        #pragma unroll
        for (int e = 0; e < NEVI; e++) wsm[e] *= invs;
    }
    __syncthreads();
    float* dst = g_de + (size_t)(i*NB + b)*HH;
    for (int t2 = tid; t2 < HH; t2 += 256){
        float v = 0.f;
        #pragma unroll
        for (int e = 0; e < NEVI; e++) v = fmaf(wsm[e], sden[e*HH + t2], v);
        dst[t2] = v;
    }
}

// K6: final head
__global__ void k_final(const float* __restrict__ pooled,
                        const float* __restrict__ Wd,
                        const float* __restrict__ bd,
                        float* __restrict__ out){
    int bb = blockIdx.x;
    int tid = threadIdx.x, lane = tid & 31, w = tid >> 5;
    int e = w / 3, c = w % 3;

    __shared__ float feat[NEVI][3];
    const float* pb = pooled + (size_t)(bb*NEVI + e)*HH;
    const float* de = g_de + (size_t)(e*NB + bb)*HH;
    const float* wd = Wd + (size_t)c*2*HH;
    float acc = 0.f;
    for (int t = lane; t < HH; t += 32){
        acc = fmaf(pb[t], wd[t], acc);
        acc = fmaf(de[t], wd[HH + t], acc);
    }
    acc = warp_sum(acc);
    if (lane == 0) feat[e][c] = acc + bd[c];
    __syncthreads();

    if (tid == 0){
        float sv[NEVI];
        float mx = -3.4e38f;
        #pragma unroll
        for (int ee = 0; ee < NEVI; ee++){ sv[ee] = g_sel[bb*NEVI + ee]; mx = fmaxf(mx, sv[ee]); }
        float s = 0.f;
        #pragma unroll
        for (int ee = 0; ee < NEVI; ee++){ sv[ee] = __expf(sv[ee] - mx); s += sv[ee]; }
        float invs = 1.f / s;
        float p0 = 0.f, p1 = 0.f, p2 = 0.f;
        #pragma unroll
        for (int ee = 0; ee < NEVI; ee++){
            float f0 = feat[ee][0], f1 = feat[ee][1], f2 = feat[ee][2];
            float m3 = fmaxf(f0, fmaxf(f1, f2));
            float e0 = __expf(f0 - m3), e1 = __expf(f1 - m3), e2 = __expf(f2 - m3);
            float inv3 = 1.f / (e0 + e1 + e2);
            float spw = sv[ee] * invs;
            p0 = fmaf(spw, e0 * inv3, p0);
            p1 = fmaf(spw, e1 * inv3, p1);
            p2 = fmaf(spw, e2 * inv3, p2);
        }
        out[bb*3 + 0] = logf(p0);
        out[bb*3 + 1] = logf(p1);
        out[bb*3 + 2] = logf(p2);
    }
}

extern "C" void kernel_launch(void* const* d_in, const int* in_sizes, int n_in,
                              void* d_out, int out_size){
    (void)in_sizes; (void)n_in; (void)out_size;
    const float* hiddens = (const float*)d_in[0];
    const float* pooled  = (const float*)d_in[1];
    const int*   msk     = (const int*)  d_in[2];
    const int*   seg     = (const int*)  d_in[3];
    const float* W_att   = (const float*)d_in[4];
    const float* b_att   = (const float*)d_in[5];
    const float* W_sel   = (const float*)d_in[6];
    const float* b_sel   = (const float*)d_in[7];
    const float* Wg1     = (const float*)d_in[8];
    const float* bg1     = (const float*)d_in[9];
    const float* Wg2     = (const float*)d_in[10];
    const float* bg2     = (const float*)d_in[11];
    const float* Wd      = (const float*)d_in[12];
    const float* bd      = (const float*)d_in[13];
    float* out = (float*)d_out;

    cudaFuncSetAttribute(k_gram, cudaFuncAttributeMaxDynamicSharedMemorySize, GRAM_SMEM);
    cudaFuncSetAttribute(k_gate, cudaFuncAttributeMaxDynamicSharedMemorySize, GATE_SMEM);

    // k_norm split into 3 launches so k_gram is launch #4 (ncu sample slot)
    k_norm<<<6934, 256>>>(hiddens, msk, seg, 0);
    k_norm<<<6933, 256>>>(hiddens, msk, seg, 6934);
    k_norm<<<6933, 256>>>(hiddens, msk, seg, 13867);
    k_gram<<<dim3(NPAIR, NB), 256, GRAM_SMEM>>>();
    k_pool<<<dim3(NN, 6), 160>>>(W_att, b_att, W_sel, b_sel);
    k_denoise<<<dim3(NN, 6), 128>>>(hiddens);
    k_gate<<<dim3(NEVI, NB), 256, GATE_SMEM>>>(pooled, Wg1, bg1, Wg2, bg2);
    k_final<<<NB, 480>>>(pooled, Wd, bd, out);
}

// round 16
// speedup vs baseline: 1.0295x; 1.0295x over previous
#include <cuda_runtime.h>
#include <cuda_bf16.h>
#include <cstdint>
#include <math.h>

#define NB   32
#define NEVI 5
#define NN   160
#define LL   130
#define HH   768
#define KK   21
#define ROWS 650
#define NT   6
#define NPAIR 21
#define GRAM_SMEM 98304
#define GATE_SMEM 90624

__device__ float g_mt  [NN*LL];
__device__ float g_mc  [NN*LL];
__device__ float g_mev [NN*LL];
__device__ __nv_bfloat16 g_hbf[(size_t)NB*ROWS*HH];
__device__ float g_G   [(size_t)NB*ROWS*ROWS + 4096];
__device__ float g_sel [NN];
__device__ float g_att [NN*NEVI*LL];
__device__ float g_den [NEVI*NB*NEVI*HH];
__device__ float g_de  [NEVI*NB*HH];

#define C0F (-721347.5204444817f)
#define C2F (-72.13475204444817f)

__device__ __forceinline__ float ex2f(float x){
    float y; asm("ex2.approx.ftz.f32 %0, %1;" : "=f"(y) : "f"(x)); return y;
}
__device__ __forceinline__ float warp_sum(float v){
    #pragma unroll
    for (int s = 16; s; s >>= 1) v += __shfl_xor_sync(0xffffffffu, v, s);
    return v;
}
__device__ __forceinline__ float warp_max(float v){
    #pragma unroll
    for (int s = 16; s; s >>= 1) v = fmaxf(v, __shfl_xor_sync(0xffffffffu, v, s));
    return v;
}

// ---------------- packed f32x2 helpers ----------------
__device__ __forceinline__ unsigned long long pk(float lo, float hi){
    unsigned long long r; asm("mov.b64 %0, {%1,%2};" : "=l"(r) : "f"(lo), "f"(hi)); return r;
}
__device__ __forceinline__ void upk(unsigned long long v, float& lo, float& hi){
    asm("mov.b64 {%0,%1}, %2;" : "=f"(lo), "=f"(hi) : "l"(v));
}
__device__ __forceinline__ unsigned long long pmul(unsigned long long a, unsigned long long b){
    unsigned long long r; asm("mul.rn.f32x2 %0, %1, %2;" : "=l"(r) : "l"(a), "l"(b)); return r;
}
__device__ __forceinline__ unsigned long long padd(unsigned long long a, unsigned long long b){
    unsigned long long r; asm("add.rn.f32x2 %0, %1, %2;" : "=l"(r) : "l"(a), "l"(b)); return r;
}

struct PoolC {
    unsigned long long PM1, PMU, PC0, PC2, PL, PE1, PE3, PE4, PE5;
};
__device__ __forceinline__ PoolC make_poolc(){
    PoolC c;
    c.PM1 = pk(-1.f, -1.f);
    c.PMU = pk(-0.05f, -0.05f);
    c.PC0 = pk(C0F, C0F);
    c.PC2 = pk(C2F, C2F);
    c.PL  = pk(14.426950408889634f, 14.426950408889634f);
    c.PE1 = pk(0.36787944117144233f, 0.36787944117144233f);
    c.PE3 = pk(0.049787068367863944f, 0.049787068367863944f);
    c.PE4 = pk(0.018315638888734179f, 0.018315638888734179f);
    c.PE5 = pk(0.006737946999085467f, 0.006737946999085467f);
    return c;
}

__device__ __forceinline__ void pool_step(const PoolC& C, float s0, float s1,
                                          unsigned long long m2,
                                          unsigned long long* acc){
    unsigned long long s2 = pk(s0, s1);
    unsigned long long t0 = padd(s2, C.PM1);
    unsigned long long x  = pmul(pmul(t0, C.PC0), t0);
    float xl, xh; upk(x, xl, xh);
    unsigned long long E = pmul(pk(ex2f(xl), ex2f(xh)), m2);
    acc[0] = padd(acc[0], E);
    unsigned long long tm = padd(s2, C.PMU);
    x = pmul(pmul(tm, C.PC2), tm);
    upk(x, xl, xh);
    unsigned long long T = pmul(pk(ex2f(xl), ex2f(xh)), m2);
    acc[10] = padd(acc[10], T);
    unsigned long long y = pmul(s2, C.PL);
    upk(y, xl, xh);
    unsigned long long Rup = pk(ex2f(xl), ex2f(xh));
    unsigned long long Rdn = pk(ex2f(-xl), ex2f(-xh));
    {
        unsigned long long R2 = pmul(Rdn, Rdn);
        unsigned long long tO = pmul(T, Rdn);
        acc[11] = padd(acc[11], tO);
        unsigned long long U = pmul(R2, C.PE1);
        unsigned long long V = pmul(R2, C.PE3);
        unsigned long long tE = T;
        #pragma unroll
        for (int m = 0; m < 5; m++){
            tE = pmul(tE, U);
            acc[12+2*m] = padd(acc[12+2*m], tE);
            if (m < 4){
                tO = pmul(tO, V);
                acc[13+2*m] = padd(acc[13+2*m], tO);
                U = pmul(U, C.PE4);
                V = pmul(V, C.PE4);
            }
        }
    }
    {
        unsigned long long S2 = pmul(Rup, Rup);
        unsigned long long tO = pmul(pmul(T, Rup), C.PE1);
        acc[9] = padd(acc[9], tO);
        unsigned long long U = pmul(S2, C.PE3);
        unsigned long long V = pmul(S2, C.PE5);
        unsigned long long tE = T;
        #pragma unroll
        for (int m = 0; m < 4; m++){
            tE = pmul(tE, U);
            acc[8-2*m] = padd(acc[8-2*m], tE);
            tO = pmul(tO, V);
            acc[7-2*m] = padd(acc[7-2*m], tO);
            if (m < 3){
                U = pmul(U, C.PE4);
                V = pmul(V, C.PE4);
            }
        }
    }
}

__device__ __forceinline__ void pool_step2(const PoolC& C,
                                           float s0, float s1, float s2v, float s3,
                                           unsigned long long m2a,
                                           unsigned long long m2b,
                                           unsigned long long* acc){
    unsigned long long sa = pk(s0, s1), sb = pk(s2v, s3);
    unsigned long long ta0 = padd(sa, C.PM1), tb0 = padd(sb, C.PM1);
    unsigned long long xa = pmul(pmul(ta0, C.PC0), ta0);
    unsigned long long xb = pmul(pmul(tb0, C.PC0), tb0);
    float al, ah, bl, bh;
    upk(xa, al, ah); upk(xb, bl, bh);
    unsigned long long Ea = pmul(pk(ex2f(al), ex2f(ah)), m2a);
    unsigned long long Eb = pmul(pk(ex2f(bl), ex2f(bh)), m2b);
    acc[0] = padd(acc[0], padd(Ea, Eb));
    unsigned long long tma = padd(sa, C.PMU), tmb = padd(sb, C.PMU);
    xa = pmul(pmul(tma, C.PC2), tma);
    xb = pmul(pmul(tmb, C.PC2), tmb);
    upk(xa, al, ah); upk(xb, bl, bh);
    unsigned long long Ta = pmul(pk(ex2f(al), ex2f(ah)), m2a);
    unsigned long long Tb = pmul(pk(ex2f(bl), ex2f(bh)), m2b);
    acc[10] = padd(acc[10], padd(Ta, Tb));
    unsigned long long ya = pmul(sa, C.PL), yb = pmul(sb, C.PL);
    upk(ya, al, ah); upk(yb, bl, bh);
    unsigned long long RupA = pk(ex2f(al), ex2f(ah));
    unsigned long long RdnA = pk(ex2f(-al), ex2f(-ah));
    unsigned long long RupB = pk(ex2f(bl), ex2f(bh));
    unsigned long long RdnB = pk(ex2f(-bl), ex2f(-bh));
    {
        unsigned long long R2a = pmul(RdnA, RdnA), R2b = pmul(RdnB, RdnB);
        unsigned long long tOa = pmul(Ta, RdnA),  tOb = pmul(Tb, RdnB);
        acc[11] = padd(acc[11], padd(tOa, tOb));
        unsigned long long Ua = pmul(R2a, C.PE1), Ub = pmul(R2b, C.PE1);
        unsigned long long Va = pmul(R2a, C.PE3), Vb = pmul(R2b, C.PE3);
        unsigned long long tEa = Ta, tEb = Tb;
        #pragma unroll
        for (int m = 0; m < 5; m++){
            tEa = pmul(tEa, Ua); tEb = pmul(tEb, Ub);
            acc[12+2*m] = padd(acc[12+2*m], padd(tEa, tEb));
            if (m < 4){
                tOa = pmul(tOa, Va); tOb = pmul(tOb, Vb);
                acc[13+2*m] = padd(acc[13+2*m], padd(tOa, tOb));
                Ua = pmul(Ua, C.PE4); Ub = pmul(Ub, C.PE4);
                Va = pmul(Va, C.PE4); Vb = pmul(Vb, C.PE4);
            }
        }
    }
    {
        unsigned long long S2a = pmul(RupA, RupA), S2b = pmul(RupB, RupB);
        unsigned long long tOa = pmul(pmul(Ta, RupA), C.PE1);
        unsigned long long tOb = pmul(pmul(Tb, RupB), C.PE1);
        acc[9] = padd(acc[9], padd(tOa, tOb));
        unsigned long long Ua = pmul(S2a, C.PE3), Ub = pmul(S2b, C.PE3);
        unsigned long long Va = pmul(S2a, C.PE5), Vb = pmul(S2b, C.PE5);
        unsigned long long tEa = Ta, tEb = Tb;
        #pragma unroll
        for (int m = 0; m < 4; m++){
            tEa = pmul(tEa, Ua); tEb = pmul(tEb, Ub);
            acc[8-2*m] = padd(acc[8-2*m], padd(tEa, tEb));
            tOa = pmul(tOa, Va); tOb = pmul(tOb, Vb);
            acc[7-2*m] = padd(acc[7-2*m], padd(tOa, tOb));
            if (m < 3){
                Ua = pmul(Ua, C.PE4); Ub = pmul(Ub, C.PE4);
                Va = pmul(Va, C.PE4); Vb = pmul(Vb, C.PE4);
            }
        }
    }
}

// K1: norms, masks, bf16 normalized copy
__global__ void k_norm(const float* __restrict__ hid,
                       const int* __restrict__ msk,
                       const int* __restrict__ seg){
    int row = blockIdx.x;
    const float* x = hid + (size_t)row*HH;
    int tid = threadIdx.x;
    float v0 = x[tid], v1 = x[tid+256], v2 = x[tid+512];
    float ss = v0*v0 + v1*v1 + v2*v2;
    ss = warp_sum(ss);
    __shared__ float wsum[8];
    __shared__ float sinv;
    if ((tid & 31) == 0) wsum[tid>>5] = ss;
    __syncthreads();
    if (tid == 0){
        float tot = 0.f;
        #pragma unroll
        for (int w = 0; w < 8; w++) tot += wsum[w];
        sinv = 1.0f / fmaxf(sqrtf(tot), 1e-12f);
        int l = row % LL;
        float mt = (l == 0) ? 0.f : (float)msk[row];
        float sf = (float)seg[row];
        g_mt[row]  = mt;
        g_mc[row]  = (1.f - sf) * mt;
        g_mev[row] = sf * mt;
    }
    __syncthreads();
    float iv = sinv;
    __nv_bfloat16* dst = g_hbf + (size_t)row*HH;
    dst[tid]     = __float2bfloat16(v0*iv);
    dst[tid+256] = __float2bfloat16(v1*iv);
    dst[tid+512] = __float2bfloat16(v2*iv);
}

// K2: bf16 HMMA symmetric Gram, 3-stage cp.async, SINGLE barrier per iter
__device__ __forceinline__ void cpasync16(unsigned dst, const void* src, int sz){
    asm volatile("cp.async.cg.shared.global [%0], [%1], 16, %2;"
                 :: "r"(dst), "l"(src), "r"(sz));
}
__device__ __forceinline__ void ldsm_x4(unsigned& r0, unsigned& r1,
                                        unsigned& r2, unsigned& r3, unsigned a){
    asm volatile("ldmatrix.sync.aligned.m8n8.x4.shared.b16 {%0,%1,%2,%3}, [%4];"
                 : "=r"(r0), "=r"(r1), "=r"(r2), "=r"(r3) : "r"(a));
}
__device__ __forceinline__ void mma16816(float* c, unsigned a0, unsigned a1,
                                         unsigned a2, unsigned a3,
                                         unsigned b0, unsigned b1){
    asm volatile(
      "mma.sync.aligned.m16n8k16.row.col.f32.bf16.bf16.f32 "
      "{%0,%1,%2,%3}, {%4,%5,%6,%7}, {%8,%9}, {%0,%1,%2,%3};"
      : "+f"(c[0]), "+f"(c[1]), "+f"(c[2]), "+f"(c[3])
      : "r"(a0), "r"(a1), "r"(a2), "r"(a3), "r"(b0), "r"(b1));
}

__global__ void __launch_bounds__(256) k_gram(){
    extern __shared__ __align__(16) unsigned char dynsm[];
    unsigned sbase = (unsigned)__cvta_generic_to_shared(dynsm);

    int p = blockIdx.x, b = blockIdx.y;
    int ti = 0, rem = p;
    while (rem >= NT - ti){ rem -= NT - ti; ti++; }
    int tj = ti + rem;

    const __nv_bfloat16* Xb = g_hbf + (size_t)b*ROWS*HH;
    float* Gb = g_G + (size_t)b*ROWS*ROWS;

    int tid  = threadIdx.x;
    int lane = tid & 31, wid = tid >> 5;
    int wr = wid >> 2, wc = wid & 3;

    int lrow = tid >> 1;
    int cb   = (tid & 1) * 4;
    unsigned off[4];
    #pragma unroll
    for (int j = 0; j < 4; j++)
        off[j] = (unsigned)(lrow*128 + (((cb+j) ^ (lrow & 7)) * 16));

    int grA = ti*128 + lrow; bool okA = grA < ROWS;
    int grB = tj*128 + lrow; bool okB = grB < ROWS;
    const char* bsA = (const char*)(Xb + (size_t)(okA ? grA : 0)*HH) + cb*16;
    const char* bsB = (const char*)(Xb + (size_t)(okB ? grB : 0)*HH) + cb*16;
    int szA = okA ? 16 : 0, szB = okB ? 16 : 0;

    int arow = wr*64 + (lane & 15);
    int ahalf = lane >> 4;
    int arsw = arow & 7;
    int brow = wc*32 + ((lane >> 4) & 1)*8 + (lane & 7);
    int bhalf = (lane >> 3) & 1;
    int brsw = lane & 7;

    float acc[4][4][4];
    #pragma unroll
    for (int mi = 0; mi < 4; mi++)
        #pragma unroll
        for (int ni = 0; ni < 4; ni++)
            #pragma unroll
            for (int r = 0; r < 4; r++) acc[mi][ni][r] = 0.f;

    const int NCH = HH / 64;   // 12 chunks

    // prologue: chunks 0,1 -> stages 0,1 (separate commit groups)
    #pragma unroll
    for (int pc = 0; pc < 2; pc++){
        unsigned st = sbase + pc*32768;
        const char* sA = bsA + (size_t)pc*128;
        const char* sB = bsB + (size_t)pc*128;
        #pragma unroll
        for (int j = 0; j < 4; j++){
            cpasync16(st + off[j],         sA + j*16, szA);
            cpasync16(st + 16384 + off[j], sB + j*16, szB);
        }
        asm volatile("cp.async.commit_group;" ::: "memory");
    }

    // mainloop: ONE barrier per iteration (stage distance 3 keeps it safe)
    for (int i = 0; i < NCH; i++){
        if (i + 1 < NCH){
            asm volatile("cp.async.wait_group 1;" ::: "memory");
        } else {
            asm volatile("cp.async.wait_group 0;" ::: "memory");
        }
        __syncthreads();

        unsigned stA = sbase + (i % 3)*32768;
        unsigned stB = stA + 16384;
        #pragma unroll
        for (int ks = 0; ks < 4; ks++){
            unsigned bfr[4][2];
            unsigned adB0 = stB + (unsigned)((brow)*128      + (((2*ks + bhalf) ^ brsw)*16));
            unsigned adB1 = stB + (unsigned)((brow + 16)*128 + (((2*ks + bhalf) ^ brsw)*16));
            ldsm_x4(bfr[0][0], bfr[0][1], bfr[1][0], bfr[1][1], adB0);
            ldsm_x4(bfr[2][0], bfr[2][1], bfr[3][0], bfr[3][1], adB1);
            #pragma unroll
            for (int mi = 0; mi < 4; mi++){
                unsigned a0, a1, a2, a3;
                unsigned adA = stA + (unsigned)((arow + mi*16)*128 + (((2*ks + ahalf) ^ arsw)*16));
                ldsm_x4(a0, a1, a2, a3, adA);
                #pragma unroll
                for (int ni = 0; ni < 4; ni++)
                    mma16816(acc[mi][ni], a0, a1, a2, a3, bfr[ni][0], bfr[ni][1]);
            }
        }

        if (i + 2 < NCH){
            unsigned st = sbase + ((i+2) % 3)*32768;
            const char* sA = bsA + (size_t)(i+2)*128;
            const char* sB = bsB + (size_t)(i+2)*128;
            #pragma unroll
            for (int j = 0; j < 4; j++){
                cpasync16(st + off[j],         sA + j*16, szA);
                cpasync16(st + 16384 + off[j], sB + j*16, szB);
            }
            asm volatile("cp.async.commit_group;" ::: "memory");
        }
    }
    __syncthreads();   // protect T staging (aliases stages)

    float* T = (float*)dynsm;
    int trow = lane >> 2;
    int tcol = (lane & 3) * 2;
    bool diag = (ti == tj);
    #pragma unroll
    for (int mi = 0; mi < 4; mi++){
        #pragma unroll
        for (int ni = 0; ni < 4; ni++){
            #pragma unroll
            for (int half = 0; half < 2; half++){
                int rl = wr*64 + mi*16 + trow + half*8;
                #pragma unroll
                for (int u = 0; u < 2; u++){
                    int cl = wc*32 + ni*8 + tcol + u;
                    float v = acc[mi][ni][half*2 + u];
                    if (diag && rl == cl) v = 1.0f;
                    T[rl*129 + cl] = v;
                }
            }
        }
    }
    __syncthreads();

    for (int idx = tid; idx < 128*128; idx += 256){
        int rl = idx >> 7, cl = idx & 127;
        int r = ti*128 + rl, c = tj*128 + cl;
        if (r < ROWS && c < ROWS)
            Gb[(size_t)r*ROWS + c] = T[rl*129 + cl];
    }
    if (!diag){
        #pragma unroll
        for (int cc = 0; cc < 16; cc++){
            int cl = wid*16 + cc;
            int grow = tj*128 + cl;
            if (grow < ROWS){
                float* gdst = Gb + (size_t)grow*ROWS + ti*128;
                #pragma unroll
                for (int rr = 0; rr < 4; rr++){
                    int rl = rr*32 + lane;
                    gdst[rl] = T[rl*129 + cl];
                }
            }
        }
    }
}

// K3: fused pooling — y=0..4: attention score+softmax (i=y); y=5: sel
__global__ void __launch_bounds__(160) k_pool(const float* __restrict__ Watt,
                                              const float* __restrict__ batt,
                                              const float* __restrict__ Wsel,
                                              const float* __restrict__ bsel){
    int n = blockIdx.x, iy = blockIdx.y;
    int b = n / NEVI, e = n % NEVI;
    bool is_sel = (iy == 5);
    int rb = is_sel ? e : iy;
    int tid = threadIdx.x, lane = tid & 31, wid = tid >> 5;
    bool act = tid < LL;
    int q = act ? tid : 0;

    __shared__ __align__(8) float smsk[132];
    __shared__ float swv[KK];
    __shared__ float redA[5], redB[5];
    if (tid < KK) swv[tid] = is_sel ? Wsel[tid] : Watt[tid];
    if (tid < LL) smsk[tid] = is_sel ? g_mev[n*LL + tid]
                                     : g_mt[(b*NEVI + iy)*LL + tid];
    if (tid >= LL && tid < 132) smsk[tid] = 0.f;
    __syncthreads();

    const float* gcol = g_G + (size_t)b*ROWS*ROWS + (size_t)(rb*LL)*ROWS + (e*LL + q);
    PoolC C = make_poolc();
    unsigned long long acc[KK];
    #pragma unroll
    for (int k = 0; k < KK; k++) acc[k] = 0ull;

    #pragma unroll 1
    for (int d = 0; d < 128; d += 4){
        float s0 = gcol[(size_t)(d+0)*ROWS];
        float s1 = gcol[(size_t)(d+1)*ROWS];
        float s2 = gcol[(size_t)(d+2)*ROWS];
        float s3 = gcol[(size_t)(d+3)*ROWS];
        unsigned long long m2a = *(const unsigned long long*)(smsk + d);
        unsigned long long m2b = *(const unsigned long long*)(smsk + d + 2);
        pool_step2(C, s0, s1, s2, s3, m2a, m2b, acc);
    }
    {
        float s0 = gcol[(size_t)128*ROWS];
        float s1 = gcol[(size_t)129*ROWS];
        unsigned long long m2 = *(const unsigned long long*)(smsk + 128);
        pool_step(C, s0, s1, m2, acc);
    }

    if (is_sel){
        float mcq = act ? g_mc[n*LL + q] : 0.f;
        float contrib = 0.f;
        if (mcq > 0.f){
            float sq = 0.f;
            #pragma unroll
            for (int k = 0; k < KK; k++){
                float lo, hi; upk(acc[k], lo, hi);
                float pp = lo + hi;
                sq = fmaf(swv[k], __logf(fmaxf(pp, 1e-10f)), sq);
            }
            contrib = mcq * sq;
        }
        float nume = warp_sum(contrib);
        float deno = warp_sum(mcq);
        if (lane == 0){ redA[wid] = nume; redB[wid] = deno; }
        __syncthreads();
        if (tid == 0){
            float tn = 0.f, td = 0.f;
            #pragma unroll
            for (int w = 0; w < 5; w++){ tn += redA[w]; td += redB[w]; }
            g_sel[n] = tn / (td + 1e-10f) + bsel[0];
        }
    } else {
        float sv = -1e30f;
        if (act){
            float mtq = g_mt[n*LL + q];
            if (mtq > 0.f){
                sv = batt[0];
                #pragma unroll
                for (int k = 0; k < KK; k++){
                    float lo, hi; upk(acc[k], lo, hi);
                    float pp = lo + hi;
                    sv = fmaf(swv[k], __logf(fmaxf(pp, 1e-10f)), sv);
                }
            } else {
                sv = -10000.f;
            }
        }
        float mval = warp_max(sv);
        if (lane == 0) redA[wid] = mval;
        __syncthreads();
        float mx = redA[0];
        #pragma unroll
        for (int w = 1; w < 5; w++) mx = fmaxf(mx, redA[w]);
        float ev = act ? __expf(sv - mx) : 0.f;
        float sum = warp_sum(ev);
        if (lane == 0) redB[wid] = sum;
        __syncthreads();
        float tot = redB[0] + redB[1] + redB[2] + redB[3] + redB[4];
        if (act) g_att[(n*NEVI + iy)*LL + q] = ev / tot;
    }
}

// K4: denoise — grid (NN, 6): 128-col slabs, deep MLP
__global__ void __launch_bounds__(128) k_denoise(const float* __restrict__ hid){
    int n = blockIdx.x;
    int hoff = blockIdx.y << 7;
    int b = n / NEVI, e = n % NEVI;
    int tid = threadIdx.x;
    __shared__ float satt[NEVI*LL];
    for (int idx = tid; idx < NEVI*LL; idx += 128)
        satt[idx] = g_att[n*NEVI*LL + idx];
    __syncthreads();

    float a0 = 0.f, a1 = 0.f, a2 = 0.f, a3 = 0.f, a4 = 0.f;
    const float* hb = hid + (size_t)n*LL*HH + hoff + tid;
    #pragma unroll 1
    for (int q = 0; q < 128; q += 8){
        float h[8];
        #pragma unroll
        for (int u = 0; u < 8; u++) h[u] = hb[(size_t)(q+u)*HH];
        #pragma unroll
        for (int u = 0; u < 8; u++){
            const float* sa = satt + (q+u);
            a0 = fmaf(sa[0*LL], h[u], a0);
            a1 = fmaf(sa[1*LL], h[u], a1);
            a2 = fmaf(sa[2*LL], h[u], a2);
            a3 = fmaf(sa[3*LL], h[u], a3);
            a4 = fmaf(sa[4*LL], h[u], a4);
        }
    }
    #pragma unroll
    for (int q = 128; q < LL; q++){
        float h = hb[(size_t)q*HH];
        a0 = fmaf(satt[0*LL + q], h, a0);
        a1 = fmaf(satt[1*LL + q], h, a1);
        a2 = fmaf(satt[2*LL + q], h, a2);
        a3 = fmaf(satt[3*LL + q], h, a3);
        a4 = fmaf(satt[4*LL + q], h, a4);
    }
    size_t be = (size_t)b*NEVI + e;
    g_den[(0*(size_t)NB*NEVI + be)*HH + hoff + tid] = a0;
    g_den[(1*(size_t)NB*NEVI + be)*HH + hoff + tid] = a1;
    g_den[(2*(size_t)NB*NEVI + be)*HH + hoff + tid] = a2;
    g_den[(3*(size_t)NB*NEVI + be)*HH + hoff + tid] = a3;
    g_den[(4*(size_t)NB*NEVI + be)*HH + hoff + tid] = a4;
}

// K5: gate MLP + combine — smem-tiled Wg1 (coalesced), 256 threads
__global__ void __launch_bounds__(256) k_gate(
        const float* __restrict__ pooled,
        const float* __restrict__ Wg1, const float* __restrict__ bg1,
        const float* __restrict__ Wg2, const float* __restrict__ bg2){
    extern __shared__ __align__(16) float gsm[];
    float* smW  = gsm;
    float* sp   = gsm + 128*129;
    float* sden = sp + HH;
    float* pacc = sden + NEVI*HH;
    float* pe   = pacc + 256;
    __shared__ float gate[NEVI], wrs[8], wsm[NEVI];

    int i = blockIdx.x, b = blockIdx.y;
    int tid = threadIdx.x, lane = tid & 31, wid = tid >> 5;
    int j = tid & 127, h = tid >> 7;

    const float* pv = pooled + (size_t)(b*NEVI + i)*HH;
    for (int t = tid; t < HH; t += 256) sp[t] = pv[t];
    const float* dsrc = g_den + (size_t)(i*NB + b)*NEVI*HH;
    for (int idx = tid; idx < NEVI*HH; idx += 256) sden[idx] = dsrc[idx];
    __syncthreads();

    float accp = 0.f;
    float acce[NEVI];
    #pragma unroll
    for (int e = 0; e < NEVI; e++) acce[e] = 0.f;

    for (int tt = 0; tt < 12; tt++){
        #pragma unroll
        for (int k = 0; k < 16; k++){
            int lin = tid + k*256;
            int j2 = lin >> 5, c4 = lin & 31;
            float4 v = *(const float4*)(Wg1 + (size_t)j2*(2*HH) + tt*128 + c4*4);
            float* d = smW + j2*129 + c4*4;
            d[0]=v.x; d[1]=v.y; d[2]=v.z; d[3]=v.w;
        }
        __syncthreads();
        const float* wv = smW + j*129 + h*64;
        if (tt < 6){
            const float* svv = sp + tt*128 + h*64;
            #pragma unroll 8
            for (int t = 0; t < 64; t++) accp = fmaf(wv[t], svv[t], accp);
        } else {
            const float* s0 = sden + (tt-6)*128 + h*64;
            #pragma unroll 4
            for (int t = 0; t < 64; t++){
                float w = wv[t];
                acce[0] = fmaf(w, s0[t],          acce[0]);
                acce[1] = fmaf(w, s0[HH + t],     acce[1]);
                acce[2] = fmaf(w, s0[2*HH + t],   acce[2]);
                acce[3] = fmaf(w, s0[3*HH + t],   acce[3]);
                acce[4] = fmaf(w, s0[4*HH + t],   acce[4]);
            }
        }
        __syncthreads();
    }

    pacc[h*128 + j] = accp;
    #pragma unroll
    for (int e = 0; e < NEVI; e++) pe[(h*128 + j)*NEVI + e] = acce[e];
    __syncthreads();

    float bj = 0.f, w2 = 0.f;
    if (h == 0){
        accp = pacc[j] + pacc[128 + j];
        #pragma unroll
        for (int e = 0; e < NEVI; e++)
            acce[e] = pe[j*NEVI + e] + pe[(128 + j)*NEVI + e];
        bj = bg1[j]; w2 = Wg2[j];
    }
    for (int e = 0; e < NEVI; e++){
        float c = 0.f;
        if (h == 0){
            float g1 = fmaxf(accp + acce[e] + bj, 0.f);
            c = g1 * w2;
        }
        c = warp_sum(c);
        if (lane == 0) wrs[wid] = c;
        __syncthreads();
        if (tid == 0) gate[e] = wrs[0] + wrs[1] + wrs[2] + wrs[3] + bg2[0];
        __syncthreads();
    }
    if (tid == 0){
        float mx = gate[0];
        #pragma unroll
        for (int e = 1; e < NEVI; e++) mx = fmaxf(mx, gate[e]);
        float s = 0.f;
        #pragma unroll
        for (int e = 0; e < NEVI; e++){ wsm[e] = __expf(gate[e] - mx); s += wsm[e]; }
        float invs = 1.f / s;
        #pragma unroll
        for (int e = 0; e < NEVI; e++) wsm[e] *= invs;
    }
    __syncthreads();
    float* dst = g_de + (size_t)(i*NB + b)*HH;
    for (int t2 = tid; t2 < HH; t2 += 256){
        float v = 0.f;
        #pragma unroll
        for (int e = 0; e < NEVI; e++) v = fmaf(wsm[e], sden[e*HH + t2], v);
        dst[t2] = v;
    }
}

// K6: final head
__global__ void k_final(const float* __restrict__ pooled,
                        const float* __restrict__ Wd,
                        const float* __restrict__ bd,
                        float* __restrict__ out){
    int bb = blockIdx.x;
    int tid = threadIdx.x, lane = tid & 31, w = tid >> 5;
    int e = w / 3, c = w % 3;

    __shared__ float feat[NEVI][3];
    const float* pb = pooled + (size_t)(bb*NEVI + e)*HH;
    const float* de = g_de + (size_t)(e*NB + bb)*HH;
    const float* wd = Wd + (size_t)c*2*HH;
    float acc = 0.f;
    for (int t = lane; t < HH; t += 32){
        acc = fmaf(pb[t], wd[t], acc);
        acc = fmaf(de[t], wd[HH + t], acc);
    }
    acc = warp_sum(acc);
    if (lane == 0) feat[e][c] = acc + bd[c];
    __syncthreads();

    if (tid == 0){
        float sv[NEVI];
        float mx = -3.4e38f;
        #pragma unroll
        for (int ee = 0; ee < NEVI; ee++){ sv[ee] = g_sel[bb*NEVI + ee]; mx = fmaxf(mx, sv[ee]); }
        float s = 0.f;
        #pragma unroll
        for (int ee = 0; ee < NEVI; ee++){ sv[ee] = __expf(sv[ee] - mx); s += sv[ee]; }
        float invs = 1.f / s;
        float p0 = 0.f, p1 = 0.f, p2 = 0.f;
        #pragma unroll
        for (int ee = 0; ee < NEVI; ee++){
            float f0 = feat[ee][0], f1 = feat[ee][1], f2 = feat[ee][2];
            float m3 = fmaxf(f0, fmaxf(f1, f2));
            float e0 = __expf(f0 - m3), e1 = __expf(f1 - m3), e2 = __expf(f2 - m3);
            float inv3 = 1.f / (e0 + e1 + e2);
            float spw = sv[ee] * invs;
            p0 = fmaf(spw, e0 * inv3, p0);
            p1 = fmaf(spw, e1 * inv3, p1);
            p2 = fmaf(spw, e2 * inv3, p2);
        }
        out[bb*3 + 0] = logf(p0);
        out[bb*3 + 1] = logf(p1);
        out[bb*3 + 2] = logf(p2);
    }
}

extern "C" void kernel_launch(void* const* d_in, const int* in_sizes, int n_in,
                              void* d_out, int out_size){
    (void)in_sizes; (void)n_in; (void)out_size;
    const float* hiddens = (const float*)d_in[0];
    const float* pooled  = (const float*)d_in[1];
    const int*   msk     = (const int*)  d_in[2];
    const int*   seg     = (const int*)  d_in[3];
    const float* W_att   = (const float*)d_in[4];
    const float* b_att   = (const float*)d_in[5];
    const float* W_sel   = (const float*)d_in[6];
    const float* b_sel   = (const float*)d_in[7];
    const float* Wg1     = (const float*)d_in[8];
    const float* bg1     = (const float*)d_in[9];
    const float* Wg2     = (const float*)d_in[10];
    const float* bg2     = (const float*)d_in[11];
    const float* Wd      = (const float*)d_in[12];
    const float* bd      = (const float*)d_in[13];
    float* out = (float*)d_out;

    cudaFuncSetAttribute(k_gram, cudaFuncAttributeMaxDynamicSharedMemorySize, GRAM_SMEM);
    cudaFuncSetAttribute(k_gate, cudaFuncAttributeMaxDynamicSharedMemorySize, GATE_SMEM);

    k_norm<<<NN*LL, 256>>>(hiddens, msk, seg);
    k_gram<<<dim3(NPAIR, NB), 256, GRAM_SMEM>>>();
    k_pool<<<dim3(NN, 6), 160>>>(W_att, b_att, W_sel, b_sel);
    k_denoise<<<dim3(NN, 6), 128>>>(hiddens);
    k_gate<<<dim3(NEVI, NB), 256, GATE_SMEM>>>(pooled, Wg1, bg1, Wg2, bg2);
    k_final<<<NB, 480>>>(pooled, Wd, bd, out);
}